// round 1
// baseline (speedup 1.0000x reference)
#include <cuda_runtime.h>
#include <math.h>

#define Bn 8
#define Cn 256
#define C2n 256
#define Hn 64
#define Wn 64
#define HWn 4096
#define KKn 9

// Scratch for stage-1 outputs (offsets clipped, mask sigmoided)
__device__ float g_offset[Bn * 18 * HWn];
__device__ float g_mask[Bn * KKn * HWn];

// ----------------------------------------------------------------------------
// Kernel A: fused offset conv (18ch, clipped to +-16) + modulator conv (9ch,
// sigmoid). Block = 256 threads = 64 pixels (tx) x 4 channel groups (ty, 64
// input channels each). Weights chunked (8 channels at a time per group) into
// static shared memory; 28-wide (27 used) float4 accumulators per thread.
// ----------------------------------------------------------------------------
__global__ __launch_bounds__(256) void offset_mask_kernel(
    const float* __restrict__ x,
    const float* __restrict__ offset_w,
    const float* __restrict__ offset_b,
    const float* __restrict__ mod_w,
    const float* __restrict__ mod_b)
{
    // per-group weight chunk [ty][72 k][28 j]; reused as reduction buffer after
    __shared__ __align__(16) float ws[4 * 72 * 28];   // 32256 B

    const int t  = threadIdx.x;
    const int ty = t >> 6;     // channel group 0..3
    const int tx = t & 63;     // pixel within block
    const int p  = blockIdx.x * 64 + tx;
    const int b  = p >> 12;
    const int s  = p & 4095;
    const int y  = s >> 6;
    const int xw = s & 63;

    float4 acc[7];
#pragma unroll
    for (int j = 0; j < 7; j++) acc[j] = make_float4(0.f, 0.f, 0.f, 0.f);

    const float* xb = x + (size_t)b * Cn * HWn;
    float* wsy = ws + ty * 2016;

    for (int cc = 0; cc < 8; cc++) {
        const int cbase = ty * 64 + cc * 8;
        __syncthreads();
        // load 8-channel weight chunk for this group: 72 k x 28 j
        for (int i = tx; i < 2016; i += 64) {
            int k = i / 28;
            int j = i - k * 28;
            int c = cbase + k / 9;
            int tap = k - (k / 9) * 9;
            float v = 0.f;
            if (j < 18)      v = offset_w[((size_t)j * Cn + c) * 9 + tap];
            else if (j < 27) v = mod_w[((size_t)(j - 18) * Cn + c) * 9 + tap];
            wsy[i] = v;
        }
        __syncthreads();
#pragma unroll 1
        for (int cl = 0; cl < 8; cl++) {
            const float* xc = xb + (size_t)(cbase + cl) * HWn;
#pragma unroll
            for (int tap = 0; tap < 9; tap++) {
                const int yy = y + tap / 3 - 1;
                const int xx = xw + tap % 3 - 1;
                float xv = 0.f;
                if ((unsigned)yy < (unsigned)Hn && (unsigned)xx < (unsigned)Wn)
                    xv = __ldg(xc + yy * Wn + xx);
                const float4* wv4 = (const float4*)(wsy + (cl * 9 + tap) * 28);
#pragma unroll
                for (int j4 = 0; j4 < 7; j4++) {
                    float4 wv = wv4[j4];
                    acc[j4].x = fmaf(xv, wv.x, acc[j4].x);
                    acc[j4].y = fmaf(xv, wv.y, acc[j4].y);
                    acc[j4].z = fmaf(xv, wv.z, acc[j4].z);
                    acc[j4].w = fmaf(xv, wv.w, acc[j4].w);
                }
            }
        }
    }

    __syncthreads();
    // cross-group reduction in smem (reuse ws): red[(ty*64+tx)*28 + j]
    float* red = ws;
#pragma unroll
    for (int j4 = 0; j4 < 7; j4++)
        ((float4*)(red + (ty * 64 + tx) * 28))[j4] = acc[j4];
    __syncthreads();

    for (int e = t; e < 64 * 27; e += 256) {
        int pl = e & 63;
        int j  = e >> 6;   // 0..26
        float sum = red[pl * 28 + j] + red[(64 + pl) * 28 + j]
                  + red[(128 + pl) * 28 + j] + red[(192 + pl) * 28 + j];
        int p2 = blockIdx.x * 64 + pl;
        int b2 = p2 >> 12;
        int s2 = p2 & 4095;
        if (j < 18) {
            float v = sum + offset_b[j];
            v = fminf(16.f, fmaxf(-16.f, v));          // max_offset = 64/4
            g_offset[(size_t)(b2 * 18 + j) * HWn + s2] = v;
        } else {
            float v = sum + mod_b[j - 18];
            g_mask[(size_t)(b2 * 9 + (j - 18)) * HWn + s2] = 1.f / (1.f + expf(-v));
        }
    }
}

// ----------------------------------------------------------------------------
// Kernel B: main deformable conv as a tiled GEMM.
// Block = 256 threads, tile = 32 pixels (half row, same b,h) x 256 co.
// Thread t owns output channel co=t and 32 pixel accumulators.
// Per block: precompute per-(pixel,tap) bilinear corner idx/weights (x mask)
// once; then per 8-channel chunk: gather val[32][72] to smem, stage
// w[256][72] to smem, FMA with float4 k-steps (v reads warp-broadcast).
// ----------------------------------------------------------------------------
__global__ __launch_bounds__(256, 2) void dfconv_kernel(
    const float* __restrict__ x,
    const float* __restrict__ reg_w,
    float* __restrict__ out)
{
    extern __shared__ __align__(16) float smem[];
    float4* tbl_w  = (float4*)smem;              // 288 entries (4608 B)
    int4*  tbl_idx = (int4*)(smem + 1152);       // 288 entries (4608 B)
    float* v_s     = smem + 2304;                // 32*72 = 2304 floats
    float* w_s     = smem + 4608;                // 256*72 = 18432 floats
    // total = 23040 floats = 92160 B

    const int t    = threadIdx.x;
    const int tile = blockIdx.x;        // 1024 tiles
    const int b    = tile >> 7;
    const int s0   = (tile & 127) * 32;
    const int h    = s0 >> 6;
    const int w0   = s0 & 63;

    // ---- build bilinear tables: 32 pixels x 9 taps ----
    for (int e = t; e < 288; e += 256) {
        int p   = e / 9;
        int tap = e - p * 9;
        int wq  = w0 + p;
        int sp  = h * Wn + wq;
        float dy = g_offset[(size_t)(b * 18 + 2 * tap) * HWn + sp];
        float dx = g_offset[(size_t)(b * 18 + 2 * tap + 1) * HWn + sp];
        float m  = g_mask[(size_t)(b * 9 + tap) * HWn + sp];
        float py = dy + (float)(tap / 3) + (float)(h - 1);
        float px = dx + (float)(tap % 3) + (float)(wq - 1);
        float y0f = floorf(py), x0f = floorf(px);
        float ly = py - y0f, lx = px - x0f;
        int y0 = (int)y0f, x0 = (int)x0f;
        int y1 = y0 + 1, x1 = x0 + 1;
        float vy0 = ((unsigned)y0 < (unsigned)Hn) ? 1.f : 0.f;
        float vy1 = ((unsigned)y1 < (unsigned)Hn) ? 1.f : 0.f;
        float vx0 = ((unsigned)x0 < (unsigned)Wn) ? 1.f : 0.f;
        float vx1 = ((unsigned)x1 < (unsigned)Wn) ? 1.f : 0.f;
        float w00 = (1.f - ly) * (1.f - lx) * m * vy0 * vx0;
        float w01 = (1.f - ly) * lx        * m * vy0 * vx1;
        float w10 = ly        * (1.f - lx) * m * vy1 * vx0;
        float w11 = ly        * lx         * m * vy1 * vx1;
        int cy0 = min(max(y0, 0), Hn - 1), cy1 = min(max(y1, 0), Hn - 1);
        int cx0 = min(max(x0, 0), Wn - 1), cx1 = min(max(x1, 0), Wn - 1);
        tbl_w[e]   = make_float4(w00, w01, w10, w11);
        tbl_idx[e] = make_int4(cy0 * Wn + cx0, cy0 * Wn + cx1,
                               cy1 * Wn + cx0, cy1 * Wn + cx1);
    }
    // (first __syncthreads inside the chunk loop publishes the tables)

    float acc[32];
#pragma unroll
    for (int p = 0; p < 32; p++) acc[p] = 0.f;

    const float* xb = x + (size_t)b * Cn * HWn;

    for (int c0 = 0; c0 < Cn; c0 += 8) {
        __syncthreads();   // guards tables (1st iter) and w_s/v_s reuse
        // stage weights: w_s[co*72 + k], k = (c_local, tap) contiguous in gmem
        for (int i = t; i < 18432; i += 256) {
            int co = i / 72;
            int k  = i - co * 72;
            w_s[i] = reg_w[(size_t)co * 2304 + c0 * 9 + k];
        }
        // gather bilinear values: v_s[p*72 + c_local*9 + tap]
        for (int e = t; e < 2304; e += 256) {
            int cl = e / 288;
            int pt = e - cl * 288;
            int p  = pt / 9;
            int tap = pt - p * 9;
            const float* xc = xb + (size_t)(c0 + cl) * HWn;
            int4   id = tbl_idx[pt];
            float4 ww = tbl_w[pt];
            float v = ww.x * __ldg(xc + id.x) + ww.y * __ldg(xc + id.y)
                    + ww.z * __ldg(xc + id.z) + ww.w * __ldg(xc + id.w);
            v_s[p * 72 + cl * 9 + tap] = v;
        }
        __syncthreads();
        // register-tiled FMA: thread = co, 32 pixel accumulators
        const float4* wrow = (const float4*)(w_s + t * 72);
#pragma unroll 1
        for (int k4 = 0; k4 < 18; k4++) {
            float4 wv = wrow[k4];
#pragma unroll
            for (int p = 0; p < 32; p++) {
                float4 vv = *(const float4*)(v_s + p * 72 + k4 * 4);
                acc[p] = fmaf(vv.x, wv.x, acc[p]);
                acc[p] = fmaf(vv.y, wv.y, acc[p]);
                acc[p] = fmaf(vv.z, wv.z, acc[p]);
                acc[p] = fmaf(vv.w, wv.w, acc[p]);
            }
        }
    }

    // write out[b][co=t][h][w0..w0+31]
    float* op = out + ((size_t)(b * C2n + t) * HWn + h * Wn + w0);
#pragma unroll
    for (int p4 = 0; p4 < 8; p4++)
        ((float4*)op)[p4] = make_float4(acc[p4 * 4], acc[p4 * 4 + 1],
                                        acc[p4 * 4 + 2], acc[p4 * 4 + 3]);
}

// ----------------------------------------------------------------------------
extern "C" void kernel_launch(void* const* d_in, const int* in_sizes, int n_in,
                              void* d_out, int out_size)
{
    const float* x        = (const float*)d_in[0];
    const float* offset_w = (const float*)d_in[1];
    const float* offset_b = (const float*)d_in[2];
    const float* mod_w    = (const float*)d_in[3];
    const float* mod_b    = (const float*)d_in[4];
    const float* reg_w    = (const float*)d_in[5];
    float* out = (float*)d_out;

    cudaFuncSetAttribute(dfconv_kernel,
                         cudaFuncAttributeMaxDynamicSharedMemorySize, 92160);

    offset_mask_kernel<<<512, 256>>>(x, offset_w, offset_b, mod_w, mod_b);
    dfconv_kernel<<<1024, 256, 92160>>>(x, reg_w, out);
}

// round 4
// speedup vs baseline: 2.9740x; 2.9740x over previous
#include <cuda_runtime.h>
#include <cuda_bf16.h>
#include <stdint.h>
#include <math.h>

#define Bn 8
#define Cn 256
#define C2n 256
#define Hn 64
#define Wn 64
#define HWn 4096
#define KKn 9
#define Ktot 2304

// ---------------- scratch ----------------
__device__ float g_offset[Bn * 18 * HWn];
__device__ float g_mask[Bn * KKn * HWn];
__device__ __align__(16) __nv_bfloat16 g_whi[C2n * Ktot];
__device__ __align__(16) __nv_bfloat16 g_wlo[C2n * Ktot];

// ---------------- warp-level MMA helpers (portable sm_80+ ISA) ----------------
__device__ __forceinline__ void ldsm4(uint32_t addr, uint32_t r[4]) {
    asm volatile("ldmatrix.sync.aligned.m8n8.x4.shared.b16 {%0,%1,%2,%3}, [%4];"
                 : "=r"(r[0]), "=r"(r[1]), "=r"(r[2]), "=r"(r[3]) : "r"(addr));
}
__device__ __forceinline__ void mma16816(float d[4], const uint32_t a[4], const uint32_t b[2]) {
    asm volatile("mma.sync.aligned.m16n8k16.row.col.f32.bf16.bf16.f32 "
                 "{%0,%1,%2,%3}, {%4,%5,%6,%7}, {%8,%9}, {%0,%1,%2,%3};"
                 : "+f"(d[0]), "+f"(d[1]), "+f"(d[2]), "+f"(d[3])
                 : "r"(a[0]), "r"(a[1]), "r"(a[2]), "r"(a[3]), "r"(b[0]), "r"(b[1]));
}
__device__ __forceinline__ uint32_t smem_to_u32(const void* p) {
    uint32_t a;
    asm("{ .reg .u64 t; cvta.to.shared.u64 t, %1; cvt.u32.u64 %0, t; }" : "=r"(a) : "l"(p));
    return a;
}

// ----------------------------------------------------------------------------
// Kernel 0: split reg_w into bf16 hi/lo in (tap, c)-major k order
// ----------------------------------------------------------------------------
__global__ __launch_bounds__(256) void prep_w_kernel(const float* __restrict__ reg_w) {
    int i = blockIdx.x * 256 + threadIdx.x;
    if (i >= C2n * Ktot) return;
    int co = i / Ktot;
    int k = i - co * Ktot;
    int tap = k >> 8;
    int c = k & 255;
    float v = reg_w[((size_t)co * Cn + c) * 9 + tap];
    __nv_bfloat16 h = __float2bfloat16(v);
    g_whi[i] = h;
    g_wlo[i] = __float2bfloat16(v - __bfloat162float(h));
}

// ----------------------------------------------------------------------------
// Kernel A: fused offset conv (18ch, clip +-16) + modulator conv (9ch, sigmoid)
// ----------------------------------------------------------------------------
__global__ __launch_bounds__(256) void offset_mask_kernel(
    const float* __restrict__ x,
    const float* __restrict__ offset_w,
    const float* __restrict__ offset_b,
    const float* __restrict__ mod_w,
    const float* __restrict__ mod_b)
{
    __shared__ __align__(16) float ws[4 * 72 * 28];

    const int t  = threadIdx.x;
    const int ty = t >> 6;
    const int tx = t & 63;
    const int p  = blockIdx.x * 64 + tx;
    const int b  = p >> 12;
    const int s  = p & 4095;
    const int y  = s >> 6;
    const int xw = s & 63;

    float4 acc[7];
#pragma unroll
    for (int j = 0; j < 7; j++) acc[j] = make_float4(0.f, 0.f, 0.f, 0.f);

    const float* xb = x + (size_t)b * Cn * HWn;
    float* wsy = ws + ty * 2016;

    for (int cc = 0; cc < 8; cc++) {
        const int cbase = ty * 64 + cc * 8;
        __syncthreads();
        for (int i = tx; i < 2016; i += 64) {
            int k = i / 28;
            int j = i - k * 28;
            int c = cbase + k / 9;
            int tap = k - (k / 9) * 9;
            float v = 0.f;
            if (j < 18)      v = offset_w[((size_t)j * Cn + c) * 9 + tap];
            else if (j < 27) v = mod_w[((size_t)(j - 18) * Cn + c) * 9 + tap];
            wsy[i] = v;
        }
        __syncthreads();
#pragma unroll 1
        for (int cl = 0; cl < 8; cl++) {
            const float* xc = xb + (size_t)(cbase + cl) * HWn;
#pragma unroll
            for (int tap = 0; tap < 9; tap++) {
                const int yy = y + tap / 3 - 1;
                const int xx = xw + tap % 3 - 1;
                float xv = 0.f;
                if ((unsigned)yy < (unsigned)Hn && (unsigned)xx < (unsigned)Wn)
                    xv = __ldg(xc + yy * Wn + xx);
                const float4* wv4 = (const float4*)(wsy + (cl * 9 + tap) * 28);
#pragma unroll
                for (int j4 = 0; j4 < 7; j4++) {
                    float4 wv = wv4[j4];
                    acc[j4].x = fmaf(xv, wv.x, acc[j4].x);
                    acc[j4].y = fmaf(xv, wv.y, acc[j4].y);
                    acc[j4].z = fmaf(xv, wv.z, acc[j4].z);
                    acc[j4].w = fmaf(xv, wv.w, acc[j4].w);
                }
            }
        }
    }

    __syncthreads();
    float* red = ws;
#pragma unroll
    for (int j4 = 0; j4 < 7; j4++)
        ((float4*)(red + (ty * 64 + tx) * 28))[j4] = acc[j4];
    __syncthreads();

    for (int e = t; e < 64 * 27; e += 256) {
        int pl = e & 63;
        int j  = e >> 6;
        float sum = red[pl * 28 + j] + red[(64 + pl) * 28 + j]
                  + red[(128 + pl) * 28 + j] + red[(192 + pl) * 28 + j];
        int p2 = blockIdx.x * 64 + pl;
        int b2 = p2 >> 12;
        int s2 = p2 & 4095;
        if (j < 18) {
            float v = sum + offset_b[j];
            v = fminf(16.f, fmaxf(-16.f, v));
            g_offset[(size_t)(b2 * 18 + j) * HWn + s2] = v;
        } else {
            float v = sum + mod_b[j - 18];
            g_mask[(size_t)(b2 * 9 + (j - 18)) * HWn + s2] = 1.f / (1.f + expf(-v));
        }
    }
}

// ----------------------------------------------------------------------------
// Kernel B: deformable conv GEMM via warp-level mma.sync (bf16x3 split, fp32
// register accumulation). CTA = 512 threads = 16 warps (2M x 8N), tile
// M=128 px x N=256 co, K=2304 in blocks of 64 (one tap x 64 channels).
// SW128-swizzled smem tiles consumed with ldmatrix.
// ----------------------------------------------------------------------------
#define OFF_TIDX 0
#define OFF_TW   18432
#define OFF_AHI  36864
#define OFF_ALO  53248
#define OFF_BHI  69632
#define OFF_BLO  102400
#define SMEM_BYTES 135168

__global__ __launch_bounds__(512, 1)
void dfconv_mma_kernel(const float* __restrict__ x, float* __restrict__ out)
{
    extern __shared__ __align__(16) char smem[];
    const uint32_t smem_base = smem_to_u32(smem);
    const int t = threadIdx.x;

    const int tile = blockIdx.x;        // 256 tiles
    const int b    = tile >> 5;
    const int sb   = (tile & 31) * 128; // spatial base within batch

    // --- bilinear tables: 128 px x 9 taps ---
    int4*   tbl_idx = (int4*)(smem + OFF_TIDX);
    float4* tbl_w   = (float4*)(smem + OFF_TW);
    for (int e = t; e < 1152; e += 512) {
        int p   = e / 9;
        int tap = e - p * 9;
        int sp  = sb + p;
        int y   = sp >> 6;
        int xw  = sp & 63;
        float dy = g_offset[(size_t)(b * 18 + 2 * tap) * HWn + sp];
        float dx = g_offset[(size_t)(b * 18 + 2 * tap + 1) * HWn + sp];
        float m  = g_mask[(size_t)(b * 9 + tap) * HWn + sp];
        float py = dy + (float)(tap / 3) + (float)(y - 1);
        float px = dx + (float)(tap % 3) + (float)(xw - 1);
        float y0f = floorf(py), x0f = floorf(px);
        float ly = py - y0f, lx = px - x0f;
        int y0 = (int)y0f, x0 = (int)x0f;
        int y1 = y0 + 1, x1 = x0 + 1;
        float vy0 = ((unsigned)y0 < (unsigned)Hn) ? 1.f : 0.f;
        float vy1 = ((unsigned)y1 < (unsigned)Hn) ? 1.f : 0.f;
        float vx0 = ((unsigned)x0 < (unsigned)Wn) ? 1.f : 0.f;
        float vx1 = ((unsigned)x1 < (unsigned)Wn) ? 1.f : 0.f;
        float w00 = (1.f - ly) * (1.f - lx) * m * vy0 * vx0;
        float w01 = (1.f - ly) * lx        * m * vy0 * vx1;
        float w10 = ly        * (1.f - lx) * m * vy1 * vx0;
        float w11 = ly        * lx         * m * vy1 * vx1;
        int cy0 = min(max(y0, 0), Hn - 1), cy1 = min(max(y1, 0), Hn - 1);
        int cx0 = min(max(x0, 0), Wn - 1), cx1 = min(max(x1, 0), Wn - 1);
        tbl_w[e]   = make_float4(w00, w01, w10, w11);
        tbl_idx[e] = make_int4(cy0 * Wn + cx0, cy0 * Wn + cx1,
                               cy1 * Wn + cx0, cy1 * Wn + cx1);
    }

    const float* xb = x + (size_t)b * Cn * HWn;
    const int p = t & 127;      // pixel owned for gathering
    const int q = t >> 7;       // channel quarter (16 channels each)

    // warp/lane decomposition for mma
    const int wid  = t >> 5;
    const int lane = t & 31;
    const int wm   = wid & 1;    // M half (64 px)
    const int wn   = wid >> 1;   // N group of 32 co

    // ldmatrix lane address components; swizzle XOR = (row&7)<<4 and all row
    // bases are multiples of 16, so row&7 == lane&7 for both A and B.
    const uint32_t lxor = (uint32_t)((lane & 7) << 4);
    const uint32_t asel = (lane & 16) ? 16u : 0u;
    const uint32_t bsel = (lane & 8) ? 16u : 0u;
    const uint32_t aRow = (uint32_t)((wm * 64 + (lane & 15)) * 128);
    const uint32_t bRow = (uint32_t)((wn * 32 + (lane & 7) + ((lane & 16) ? 8 : 0)) * 128);
    const uint32_t aAddrH = smem_base + OFF_AHI + aRow;
    const uint32_t aAddrL = smem_base + OFF_ALO + aRow;
    const uint32_t bAddrH = smem_base + OFF_BHI + bRow;
    const uint32_t bAddrL = smem_base + OFF_BLO + bRow;

    float d[4][4][4];
#pragma unroll
    for (int mt = 0; mt < 4; mt++)
#pragma unroll
        for (int nt = 0; nt < 4; nt++)
#pragma unroll
            for (int j = 0; j < 4; j++) d[mt][nt][j] = 0.f;

#pragma unroll 1
    for (int kb = 0; kb < 36; kb++) {
        const int tap = kb >> 2;
        const int c0  = (kb & 3) * 64;
        const int kbase = kb * 64;

        __syncthreads();   // tables ready (1st iter); previous mma reads done

        // --- stage B tile: 256 co x 64 k, hi + lo ---
        for (int i = t; i < 4096; i += 512) {
            int hl = i >> 11;
            int ci = i & 2047;
            int co = ci >> 3;
            int k8 = ci & 7;
            const __nv_bfloat16* src = (hl ? g_wlo : g_whi)
                                       + (size_t)co * Ktot + kbase + k8 * 8;
            uint4 v = *(const uint4*)src;
            uint32_t so = (uint32_t)(co * 128 + ((k8 * 16) ^ ((co & 7) << 4)));
            *(uint4*)(smem + (hl ? OFF_BLO : OFF_BHI) + so) = v;
        }

        // --- gather A tile: 128 px x 64 c (this tap), split hi/lo bf16 ---
        {
            int4   id = tbl_idx[p * 9 + tap];
            float4 wt = tbl_w[p * 9 + tap];
            const float* xpb = xb + (size_t)(c0 + q * 16) * HWn;
            const uint32_t pxor = (uint32_t)((p & 7) << 4);
#pragma unroll
            for (int it = 0; it < 8; it++) {
                const float* xc0 = xpb + (size_t)(it * 2) * HWn;
                const float* xc1 = xc0 + HWn;
                float v0 = wt.x * __ldg(xc0 + id.x) + wt.y * __ldg(xc0 + id.y)
                         + wt.z * __ldg(xc0 + id.z) + wt.w * __ldg(xc0 + id.w);
                float v1 = wt.x * __ldg(xc1 + id.x) + wt.y * __ldg(xc1 + id.y)
                         + wt.z * __ldg(xc1 + id.z) + wt.w * __ldg(xc1 + id.w);
                __nv_bfloat16 h0 = __float2bfloat16(v0);
                __nv_bfloat16 h1 = __float2bfloat16(v1);
                __nv_bfloat16 l0 = __float2bfloat16(v0 - __bfloat162float(h0));
                __nv_bfloat16 l1 = __float2bfloat16(v1 - __bfloat162float(h1));
                uint32_t hp = (uint32_t)__bfloat16_as_ushort(h0)
                            | ((uint32_t)__bfloat16_as_ushort(h1) << 16);
                uint32_t lp = (uint32_t)__bfloat16_as_ushort(l0)
                            | ((uint32_t)__bfloat16_as_ushort(l1) << 16);
                uint32_t so = (uint32_t)(p * 128 + ((q * 32 + it * 4) ^ pxor));
                *(uint32_t*)(smem + OFF_AHI + so) = hp;
                *(uint32_t*)(smem + OFF_ALO + so) = lp;
            }
        }

        __syncthreads();

        // --- mma: 4 k-steps x (Ah*Bh + Al*Bh + Ah*Bl) ---
#pragma unroll
        for (int ks = 0; ks < 4; ks++) {
            const uint32_t acol = (uint32_t)((ks * 32 + asel) ^ lxor);
            const uint32_t bcol = (uint32_t)((ks * 32 + bsel) ^ lxor);
            uint32_t Ah[4][4], Al[4][4], Bf[2][4];
#pragma unroll
            for (int mt = 0; mt < 4; mt++) {
                ldsm4(aAddrH + mt * 2048 + acol, Ah[mt]);
                ldsm4(aAddrL + mt * 2048 + acol, Al[mt]);
            }
            ldsm4(bAddrH + bcol, Bf[0]);
            ldsm4(bAddrH + 2048 + bcol, Bf[1]);
#pragma unroll
            for (int mt = 0; mt < 4; mt++)
#pragma unroll
                for (int nt = 0; nt < 4; nt++) {
                    const uint32_t* bp = &Bf[nt >> 1][(nt & 1) * 2];
                    mma16816(d[mt][nt], Ah[mt], bp);
                    mma16816(d[mt][nt], Al[mt], bp);
                }
            ldsm4(bAddrL + bcol, Bf[0]);
            ldsm4(bAddrL + 2048 + bcol, Bf[1]);
#pragma unroll
            for (int mt = 0; mt < 4; mt++)
#pragma unroll
                for (int nt = 0; nt < 4; nt++) {
                    const uint32_t* bp = &Bf[nt >> 1][(nt & 1) * 2];
                    mma16816(d[mt][nt], Ah[mt], bp);
                }
        }
    }

    // --- epilogue: d[mt][nt] -> out[b][co][sb + px] ---
    {
        const int g   = lane >> 2;
        const int tig = lane & 3;
        float* outb = out + (size_t)b * C2n * HWn + sb;
#pragma unroll
        for (int mt = 0; mt < 4; mt++) {
            const int px0 = wm * 64 + mt * 16 + g;
#pragma unroll
            for (int nt = 0; nt < 4; nt++) {
                const int co0 = wn * 32 + nt * 8 + tig * 2;
                outb[(size_t)co0 * HWn + px0]           = d[mt][nt][0];
                outb[(size_t)(co0 + 1) * HWn + px0]     = d[mt][nt][1];
                outb[(size_t)co0 * HWn + px0 + 8]       = d[mt][nt][2];
                outb[(size_t)(co0 + 1) * HWn + px0 + 8] = d[mt][nt][3];
            }
        }
    }
}

// ----------------------------------------------------------------------------
extern "C" void kernel_launch(void* const* d_in, const int* in_sizes, int n_in,
                              void* d_out, int out_size)
{
    const float* x        = (const float*)d_in[0];
    const float* offset_w = (const float*)d_in[1];
    const float* offset_b = (const float*)d_in[2];
    const float* mod_w    = (const float*)d_in[3];
    const float* mod_b    = (const float*)d_in[4];
    const float* reg_w    = (const float*)d_in[5];
    float* out = (float*)d_out;

    cudaFuncSetAttribute(dfconv_mma_kernel,
                         cudaFuncAttributeMaxDynamicSharedMemorySize, SMEM_BYTES);

    prep_w_kernel<<<(C2n * Ktot + 255) / 256, 256>>>(reg_w);
    offset_mask_kernel<<<512, 256>>>(x, offset_w, offset_b, mod_w, mod_b);
    dfconv_mma_kernel<<<256, 512, SMEM_BYTES>>>(x, out);
}

// round 6
// speedup vs baseline: 4.1317x; 1.3893x over previous
#include <cuda_runtime.h>
#include <cuda_bf16.h>
#include <stdint.h>
#include <string.h>
#include <math.h>

#define Bn 8
#define Cn 256
#define C2n 256
#define Hn 64
#define Wn 64
#define HWn 4096
#define KKn 9
#define Ktot 2304

// ---------------- device scratch ----------------
__device__ float g_offset[Bn * 18 * HWn];
__device__ float g_mask[Bn * KKn * HWn];
__device__ __align__(16) __nv_bfloat16 g_whi[C2n * Ktot];
__device__ __align__(16) __nv_bfloat16 g_wlo[C2n * Ktot];
__device__ __align__(16) __nv_bfloat16 g_omhi[32 * Ktot];
__device__ __align__(16) __nv_bfloat16 g_omlo[32 * Ktot];
// x transposed to NHWC, bf16 hi/lo split: xt[b][y][w][c]
__device__ __align__(16) __nv_bfloat16 g_xhi[(size_t)Bn * HWn * Cn];
__device__ __align__(16) __nv_bfloat16 g_xlo[(size_t)Bn * HWn * Cn];

// ---------------- warp-level MMA helpers ----------------
__device__ __forceinline__ void ldsm4(uint32_t addr, uint32_t r[4]) {
    asm volatile("ldmatrix.sync.aligned.m8n8.x4.shared.b16 {%0,%1,%2,%3}, [%4];"
                 : "=r"(r[0]), "=r"(r[1]), "=r"(r[2]), "=r"(r[3]) : "r"(addr));
}
__device__ __forceinline__ void mma16816(float d[4], const uint32_t a[4], const uint32_t b[2]) {
    asm volatile("mma.sync.aligned.m16n8k16.row.col.f32.bf16.bf16.f32 "
                 "{%0,%1,%2,%3}, {%4,%5,%6,%7}, {%8,%9}, {%0,%1,%2,%3};"
                 : "+f"(d[0]), "+f"(d[1]), "+f"(d[2]), "+f"(d[3])
                 : "r"(a[0]), "r"(a[1]), "r"(a[2]), "r"(a[3]), "r"(b[0]), "r"(b[1]));
}
__device__ __forceinline__ uint32_t smem_to_u32(const void* p) {
    uint32_t a;
    asm("{ .reg .u64 t; cvta.to.shared.u64 t, %1; cvt.u32.u64 %0, t; }" : "=r"(a) : "l"(p));
    return a;
}
__device__ __forceinline__ float2 bf2f(uint32_t u) {
    __nv_bfloat162 h = *reinterpret_cast<__nv_bfloat162*>(&u);
    return __bfloat1622float2(h);
}
// accumulate 8 channels: v[i] += w * (hi[i] + lo[i])
__device__ __forceinline__ void accum8(float v[8], uint4 h, uint4 l, float w) {
    float2 a, bb;
    a = bf2f(h.x); bb = bf2f(l.x); v[0] = fmaf(w, a.x + bb.x, v[0]); v[1] = fmaf(w, a.y + bb.y, v[1]);
    a = bf2f(h.y); bb = bf2f(l.y); v[2] = fmaf(w, a.x + bb.x, v[2]); v[3] = fmaf(w, a.y + bb.y, v[3]);
    a = bf2f(h.z); bb = bf2f(l.z); v[4] = fmaf(w, a.x + bb.x, v[4]); v[5] = fmaf(w, a.y + bb.y, v[5]);
    a = bf2f(h.w); bb = bf2f(l.w); v[6] = fmaf(w, a.x + bb.x, v[6]); v[7] = fmaf(w, a.y + bb.y, v[7]);
}
__device__ __forceinline__ uint32_t pack_hi(float a, float b, float& ra, float& rb) {
    __nv_bfloat16 ha = __float2bfloat16(a);
    __nv_bfloat16 hb = __float2bfloat16(b);
    ra = a - __bfloat162float(ha);
    rb = b - __bfloat162float(hb);
    __nv_bfloat162 p = __halves2bfloat162(ha, hb);
    return *reinterpret_cast<uint32_t*>(&p);
}
__device__ __forceinline__ uint32_t pack_bf2(float a, float b) {
    __nv_bfloat162 p = __floats2bfloat162_rn(a, b);
    return *reinterpret_cast<uint32_t*>(&p);
}

// ----------------------------------------------------------------------------
// prep 1: reg_w -> bf16 hi/lo, k = tap*256 + c ordering
// ----------------------------------------------------------------------------
__global__ __launch_bounds__(256) void prep_w_kernel(const float* __restrict__ reg_w) {
    int i = blockIdx.x * 256 + threadIdx.x;
    if (i >= C2n * Ktot) return;
    int co = i / Ktot;
    int k = i - co * Ktot;
    int tap = k >> 8;
    int c = k & 255;
    float v = reg_w[((size_t)co * Cn + c) * 9 + tap];
    __nv_bfloat16 h = __float2bfloat16(v);
    g_whi[i] = h;
    g_wlo[i] = __float2bfloat16(v - __bfloat162float(h));
}

// ----------------------------------------------------------------------------
// prep 2: offset_w (18) + mod_w (9) packed as 32 output rows, same k order
// ----------------------------------------------------------------------------
__global__ __launch_bounds__(256) void prep_wom_kernel(
    const float* __restrict__ offset_w, const float* __restrict__ mod_w) {
    int i = blockIdx.x * 256 + threadIdx.x;
    if (i >= 32 * Ktot) return;
    int j = i / Ktot;
    int k = i - j * Ktot;
    int tap = k >> 8;
    int c = k & 255;
    float v = 0.f;
    if (j < 18)      v = offset_w[((size_t)j * Cn + c) * 9 + tap];
    else if (j < 27) v = mod_w[((size_t)(j - 18) * Cn + c) * 9 + tap];
    __nv_bfloat16 h = __float2bfloat16(v);
    g_omhi[i] = h;
    g_omlo[i] = __float2bfloat16(v - __bfloat162float(h));
}

// ----------------------------------------------------------------------------
// prep 3: NCHW fp32 x -> NHWC bf16 hi/lo (xt[b][y][w][c])
// ----------------------------------------------------------------------------
__global__ __launch_bounds__(256) void prep_xt_kernel(const float* __restrict__ x) {
    extern __shared__ float tile[];   // 256 * 65 floats
    const int t = threadIdx.x;
    const int b = blockIdx.x >> 6;
    const int y = blockIdx.x & 63;
    const float* xs = x + (size_t)b * Cn * HWn + y * Wn;
    for (int i = t; i < 16384; i += 256) {
        int c = i >> 6;
        int w = i & 63;
        tile[c * 65 + w] = xs[(size_t)c * HWn + w];
    }
    __syncthreads();
    const size_t obase = ((size_t)(b * 64 + y) * 64) * 256;
    for (int i = t; i < 16384; i += 256) {
        int c = i & 255;
        int w = i >> 8;
        float v = tile[c * 65 + w];
        __nv_bfloat16 h = __float2bfloat16(v);
        g_xhi[obase + (size_t)w * 256 + c] = h;
        g_xlo[obase + (size_t)w * 256 + c] = __float2bfloat16(v - __bfloat162float(h));
    }
}

// ----------------------------------------------------------------------------
// Kernel A: offset + modulator conv as mma GEMM (N=32 incl. 5 pad rows).
// CTA = 256 threads = 8 warps (4M x 2N), tile M=128 px x N=32 j,
// K=2304 in blocks of 64 (tap x 64c). bf16x3 split, fp32 accum.
// ----------------------------------------------------------------------------
#define OA_HI 0
#define OA_LO 16384
#define OB_HI 32768
#define OB_LO 36864

__global__ __launch_bounds__(256, 2) void offmask_mma_kernel(
    const float* __restrict__ offset_b, const float* __restrict__ mod_b)
{
    __shared__ __align__(16) char osm[40960];
    const uint32_t osb = smem_to_u32(osm);
    const int t = threadIdx.x;

    const int tile = blockIdx.x;       // 256 tiles
    const int b    = tile >> 5;
    const int sb   = (tile & 31) * 128;

    const int wid  = t >> 5;
    const int lane = t & 31;
    const int wm   = wid & 3;          // 32-px group
    const int wn   = wid >> 2;         // 16-j group

    const uint32_t lxor = (uint32_t)((lane & 7) << 4);
    const uint32_t asel = (lane & 16) ? 16u : 0u;
    const uint32_t bsel = (lane & 8) ? 16u : 0u;
    const uint32_t aAddrH = osb + OA_HI + (uint32_t)((wm * 32 + (lane & 15)) * 128);
    const uint32_t aAddrL = osb + OA_LO + (uint32_t)((wm * 32 + (lane & 15)) * 128);
    const uint32_t bAddrH = osb + OB_HI + (uint32_t)(((wn * 16 + (lane & 7) + ((lane & 16) ? 8 : 0))) * 128);
    const uint32_t bAddrL = osb + OB_LO + (uint32_t)(((wn * 16 + (lane & 7) + ((lane & 16) ? 8 : 0))) * 128);

    // A staging role: px + 32-channel half
    const int spx = t >> 1;
    const int ch  = (t & 1) * 32;
    const int ssp = sb + spx;
    const int sy  = ssp >> 6;
    const int sxw = ssp & 63;
    const uint32_t arow = (uint32_t)(spx * 128);
    const uint32_t pxor2 = (uint32_t)((spx & 7) << 4);

    float d[2][2][4];
#pragma unroll
    for (int mt = 0; mt < 2; mt++)
#pragma unroll
        for (int nt = 0; nt < 2; nt++)
#pragma unroll
            for (int j = 0; j < 4; j++) d[mt][nt][j] = 0.f;

#pragma unroll 1
    for (int kb = 0; kb < 36; kb++) {
        const int tap = kb >> 2;
        const int c0  = (kb & 3) * 64;
        const int kbase = kb * 64;

        __syncthreads();

        // stage B: 32 j x 64 k (128 B/row), hi + lo — 256 chunks of 16 B
        {
            int j  = t >> 3;          // 0..31
            int ku = t & 7;           // 0..7 (8 bf16 = 16 B)
            uint32_t dst = (uint32_t)(j * 128 + ((ku * 16) ^ ((j & 7) << 4)));
            *(uint4*)(osm + OB_HI + dst) = *(const uint4*)(g_omhi + (size_t)j * Ktot + kbase + ku * 8);
            *(uint4*)(osm + OB_LO + dst) = *(const uint4*)(g_omlo + (size_t)j * Ktot + kbase + ku * 8);
        }

        // stage A: regular shifted taps from NHWC xt (coalesced)
        {
            const int py  = sy + tap / 3 - 1;
            const int pxx = sxw + tap % 3 - 1;
            const bool valid = ((unsigned)py < (unsigned)Hn) && ((unsigned)pxx < (unsigned)Wn);
            if (valid) {
                const size_t src = ((size_t)(b * 4096 + py * 64 + pxx)) * 256 + c0 + ch;
                const uint4* ph = (const uint4*)(g_xhi + src);
                const uint4* pl = (const uint4*)(g_xlo + src);
#pragma unroll
                for (int u = 0; u < 4; u++) {
                    uint32_t o = (uint32_t)((ch * 2 + u * 16) ^ pxor2);
                    *(uint4*)(osm + OA_HI + arow + o) = ph[u];
                    *(uint4*)(osm + OA_LO + arow + o) = pl[u];
                }
            } else {
                uint4 z = make_uint4(0, 0, 0, 0);
#pragma unroll
                for (int u = 0; u < 4; u++) {
                    uint32_t o = (uint32_t)((ch * 2 + u * 16) ^ pxor2);
                    *(uint4*)(osm + OA_HI + arow + o) = z;
                    *(uint4*)(osm + OA_LO + arow + o) = z;
                }
            }
        }

        __syncthreads();

#pragma unroll
        for (int ks = 0; ks < 4; ks++) {
            const uint32_t acol = (uint32_t)((ks * 32 + asel) ^ lxor);
            const uint32_t bcol = (uint32_t)((ks * 32 + bsel) ^ lxor);
            uint32_t Ah[2][4], Al[2][4], BH[4], BL[4];
#pragma unroll
            for (int mt = 0; mt < 2; mt++) {
                ldsm4(aAddrH + mt * 2048 + acol, Ah[mt]);
                ldsm4(aAddrL + mt * 2048 + acol, Al[mt]);
            }
            ldsm4(bAddrH + bcol, BH);
            ldsm4(bAddrL + bcol, BL);
#pragma unroll
            for (int mt = 0; mt < 2; mt++)
#pragma unroll
                for (int nt = 0; nt < 2; nt++) {
                    mma16816(d[mt][nt], Ah[mt], &BH[nt * 2]);
                    mma16816(d[mt][nt], Al[mt], &BH[nt * 2]);
                    mma16816(d[mt][nt], Ah[mt], &BL[nt * 2]);
                }
        }
    }

    // epilogue: clip/sigmoid, write g_offset / g_mask
    {
        const int g   = lane >> 2;
        const int tig = lane & 3;
#pragma unroll
        for (int mt = 0; mt < 2; mt++) {
#pragma unroll
            for (int nt = 0; nt < 2; nt++) {
#pragma unroll
                for (int r = 0; r < 4; r++) {
                    int px = wm * 32 + mt * 16 + g + ((r >= 2) ? 8 : 0);
                    int j  = wn * 16 + nt * 8 + tig * 2 + (r & 1);
                    int sp = sb + px;
                    float v = d[mt][nt][r];
                    if (j < 18) {
                        float o = fminf(16.f, fmaxf(-16.f, v + offset_b[j]));
                        g_offset[(size_t)(b * 18 + j) * HWn + sp] = o;
                    } else if (j < 27) {
                        float o = v + mod_b[j - 18];
                        g_mask[(size_t)(b * 9 + (j - 18)) * HWn + sp] = 1.f / (1.f + expf(-o));
                    }
                }
            }
        }
    }
}

// ----------------------------------------------------------------------------
// Kernel B: deformable conv GEMM via mma.sync (bf16x3), NHWC-coalesced gather.
// CTA = 512 threads = 16 warps (2M x 8N), tile M=128 px x N=256 co,
// K=2304 in blocks of 64 (tap x 64c).
// ----------------------------------------------------------------------------
#define OFF_TIDX 0
#define OFF_TW   18432
#define OFF_AHI  36864
#define OFF_ALO  53248
#define OFF_BHI  69632
#define OFF_BLO  102400
#define SMEM_BYTES 135168

__global__ __launch_bounds__(512, 1)
void dfconv_mma_kernel(float* __restrict__ out)
{
    extern __shared__ __align__(16) char smem[];
    const uint32_t smem_base = smem_to_u32(smem);
    const int t = threadIdx.x;

    const int tile = blockIdx.x;        // 256 tiles
    const int b    = tile >> 5;
    const int sb   = (tile & 31) * 128;

    // --- bilinear tables: 128 px x 9 taps ---
    int4*   tbl_idx = (int4*)(smem + OFF_TIDX);
    float4* tbl_w   = (float4*)(smem + OFF_TW);
    for (int e = t; e < 1152; e += 512) {
        int p   = e / 9;
        int tap = e - p * 9;
        int sp  = sb + p;
        int y   = sp >> 6;
        int xw  = sp & 63;
        float dy = g_offset[(size_t)(b * 18 + 2 * tap) * HWn + sp];
        float dx = g_offset[(size_t)(b * 18 + 2 * tap + 1) * HWn + sp];
        float m  = g_mask[(size_t)(b * 9 + tap) * HWn + sp];
        float py = dy + (float)(tap / 3) + (float)(y - 1);
        float px = dx + (float)(tap % 3) + (float)(xw - 1);
        float y0f = floorf(py), x0f = floorf(px);
        float ly = py - y0f, lx = px - x0f;
        int y0 = (int)y0f, x0 = (int)x0f;
        int y1 = y0 + 1, x1 = x0 + 1;
        float vy0 = ((unsigned)y0 < (unsigned)Hn) ? 1.f : 0.f;
        float vy1 = ((unsigned)y1 < (unsigned)Hn) ? 1.f : 0.f;
        float vx0 = ((unsigned)x0 < (unsigned)Wn) ? 1.f : 0.f;
        float vx1 = ((unsigned)x1 < (unsigned)Wn) ? 1.f : 0.f;
        float w00 = (1.f - ly) * (1.f - lx) * m * vy0 * vx0;
        float w01 = (1.f - ly) * lx        * m * vy0 * vx1;
        float w10 = ly        * (1.f - lx) * m * vy1 * vx0;
        float w11 = ly        * lx         * m * vy1 * vx1;
        int cy0 = min(max(y0, 0), Hn - 1), cy1 = min(max(y1, 0), Hn - 1);
        int cx0 = min(max(x0, 0), Wn - 1), cx1 = min(max(x1, 0), Wn - 1);
        tbl_w[e]   = make_float4(w00, w01, w10, w11);
        tbl_idx[e] = make_int4(cy0 * Wn + cx0, cy0 * Wn + cx1,
                               cy1 * Wn + cx0, cy1 * Wn + cx1);
    }

    // gather role: px + 16-channel group
    const int gpx = t >> 2;
    const int cg  = t & 3;
    const uint32_t grow  = (uint32_t)(gpx * 128);
    const uint32_t pxor  = (uint32_t)((gpx & 7) << 4);

    // mma role
    const int wid  = t >> 5;
    const int lane = t & 31;
    const int wm   = wid & 1;
    const int wn   = wid >> 1;
    const uint32_t lxor = (uint32_t)((lane & 7) << 4);
    const uint32_t asel = (lane & 16) ? 16u : 0u;
    const uint32_t bsel = (lane & 8) ? 16u : 0u;
    const uint32_t aRow = (uint32_t)((wm * 64 + (lane & 15)) * 128);
    const uint32_t bRow = (uint32_t)((wn * 32 + (lane & 7) + ((lane & 16) ? 8 : 0)) * 128);
    const uint32_t aAddrH = smem_base + OFF_AHI + aRow;
    const uint32_t aAddrL = smem_base + OFF_ALO + aRow;
    const uint32_t bAddrH = smem_base + OFF_BHI + bRow;
    const uint32_t bAddrL = smem_base + OFF_BLO + bRow;

    float d[4][4][4];
#pragma unroll
    for (int mt = 0; mt < 4; mt++)
#pragma unroll
        for (int nt = 0; nt < 4; nt++)
#pragma unroll
            for (int j = 0; j < 4; j++) d[mt][nt][j] = 0.f;

#pragma unroll 1
    for (int kb = 0; kb < 36; kb++) {
        const int tap = kb >> 2;
        const int c0  = (kb & 3) * 64;
        const int kbase = kb * 64;

        __syncthreads();

        // --- stage B tile: 256 co x 64 k, hi + lo ---
        for (int i = t; i < 4096; i += 512) {
            int hl = i >> 11;
            int ci = i & 2047;
            int co = ci >> 3;
            int k8 = ci & 7;
            const __nv_bfloat16* src = (hl ? g_wlo : g_whi)
                                       + (size_t)co * Ktot + kbase + k8 * 8;
            uint4 v = *(const uint4*)src;
            uint32_t so = (uint32_t)(co * 128 + ((k8 * 16) ^ ((co & 7) << 4)));
            *(uint4*)(smem + (hl ? OFF_BLO : OFF_BHI) + so) = v;
        }

        // --- gather A tile: NHWC-coalesced bilinear, split hi/lo bf16 ---
        {
            int4   id = tbl_idx[gpx * 9 + tap];
            float4 wt = tbl_w[gpx * 9 + tap];
            const size_t cbase = ((size_t)b * 4096) * 256 + c0 + cg * 16;
            const size_t o0 = cbase + (size_t)id.x * 256;
            const size_t o1 = cbase + (size_t)id.y * 256;
            const size_t o2 = cbase + (size_t)id.z * 256;
            const size_t o3 = cbase + (size_t)id.w * 256;
#pragma unroll
            for (int u = 0; u < 2; u++) {
                float v[8];
#pragma unroll
                for (int i = 0; i < 8; i++) v[i] = 0.f;
                accum8(v, ((const uint4*)(g_xhi + o0))[u], ((const uint4*)(g_xlo + o0))[u], wt.x);
                accum8(v, ((const uint4*)(g_xhi + o1))[u], ((const uint4*)(g_xlo + o1))[u], wt.y);
                accum8(v, ((const uint4*)(g_xhi + o2))[u], ((const uint4*)(g_xlo + o2))[u], wt.z);
                accum8(v, ((const uint4*)(g_xhi + o3))[u], ((const uint4*)(g_xlo + o3))[u], wt.w);
                float r[8];
                uint4 H, L;
                H.x = pack_hi(v[0], v[1], r[0], r[1]);
                H.y = pack_hi(v[2], v[3], r[2], r[3]);
                H.z = pack_hi(v[4], v[5], r[4], r[5]);
                H.w = pack_hi(v[6], v[7], r[6], r[7]);
                L.x = pack_bf2(r[0], r[1]);
                L.y = pack_bf2(r[2], r[3]);
                L.z = pack_bf2(r[4], r[5]);
                L.w = pack_bf2(r[6], r[7]);
                uint32_t o = (uint32_t)((cg * 32 + u * 16) ^ pxor);
                *(uint4*)(smem + OFF_AHI + grow + o) = H;
                *(uint4*)(smem + OFF_ALO + grow + o) = L;
            }
        }

        __syncthreads();

        // --- mma: 4 k-steps x (Ah*Bh + Al*Bh + Ah*Bl) ---
#pragma unroll
        for (int ks = 0; ks < 4; ks++) {
            const uint32_t acol = (uint32_t)((ks * 32 + asel) ^ lxor);
            const uint32_t bcol = (uint32_t)((ks * 32 + bsel) ^ lxor);
            uint32_t Ah[4][4], Al[4][4], Bf[2][4];
#pragma unroll
            for (int mt = 0; mt < 4; mt++) {
                ldsm4(aAddrH + mt * 2048 + acol, Ah[mt]);
                ldsm4(aAddrL + mt * 2048 + acol, Al[mt]);
            }
            ldsm4(bAddrH + bcol, Bf[0]);
            ldsm4(bAddrH + 2048 + bcol, Bf[1]);
#pragma unroll
            for (int mt = 0; mt < 4; mt++)
#pragma unroll
                for (int nt = 0; nt < 4; nt++) {
                    const uint32_t* bp = &Bf[nt >> 1][(nt & 1) * 2];
                    mma16816(d[mt][nt], Ah[mt], bp);
                    mma16816(d[mt][nt], Al[mt], bp);
                }
            ldsm4(bAddrL + bcol, Bf[0]);
            ldsm4(bAddrL + 2048 + bcol, Bf[1]);
#pragma unroll
            for (int mt = 0; mt < 4; mt++)
#pragma unroll
                for (int nt = 0; nt < 4; nt++) {
                    const uint32_t* bp = &Bf[nt >> 1][(nt & 1) * 2];
                    mma16816(d[mt][nt], Ah[mt], bp);
                }
        }
    }

    // --- epilogue ---
    {
        const int g   = lane >> 2;
        const int tig = lane & 3;
        float* outb = out + (size_t)b * C2n * HWn + sb;
#pragma unroll
        for (int mt = 0; mt < 4; mt++) {
            const int px0 = wm * 64 + mt * 16 + g;
#pragma unroll
            for (int nt = 0; nt < 4; nt++) {
                const int co0 = wn * 32 + nt * 8 + tig * 2;
                outb[(size_t)co0 * HWn + px0]           = d[mt][nt][0];
                outb[(size_t)(co0 + 1) * HWn + px0]     = d[mt][nt][1];
                outb[(size_t)co0 * HWn + px0 + 8]       = d[mt][nt][2];
                outb[(size_t)(co0 + 1) * HWn + px0 + 8] = d[mt][nt][3];
            }
        }
    }
}

// ----------------------------------------------------------------------------
extern "C" void kernel_launch(void* const* d_in, const int* in_sizes, int n_in,
                              void* d_out, int out_size)
{
    const float* x        = (const float*)d_in[0];
    const float* offset_w = (const float*)d_in[1];
    const float* offset_b = (const float*)d_in[2];
    const float* mod_w    = (const float*)d_in[3];
    const float* mod_b    = (const float*)d_in[4];
    const float* reg_w    = (const float*)d_in[5];
    float* out = (float*)d_out;

    cudaFuncSetAttribute(dfconv_mma_kernel,
                         cudaFuncAttributeMaxDynamicSharedMemorySize, SMEM_BYTES);
    cudaFuncSetAttribute(prep_xt_kernel,
                         cudaFuncAttributeMaxDynamicSharedMemorySize, 256 * 65 * 4);

    prep_w_kernel<<<(C2n * Ktot + 255) / 256, 256>>>(reg_w);
    prep_wom_kernel<<<(32 * Ktot + 255) / 256, 256>>>(offset_w, mod_w);
    prep_xt_kernel<<<512, 256, 256 * 65 * 4>>>(x);
    offmask_mma_kernel<<<256, 256>>>(offset_b, mod_b);
    dfconv_mma_kernel<<<256, 512, SMEM_BYTES>>>(out);
}